// round 10
// baseline (speedup 1.0000x reference)
#include <cuda_runtime.h>
#include <stdint.h>

#define GH 52
#define GW 52
#define NB 5
#define NBOX 13520                 // 52*52*5
#define ROWBITS 288                // padded positions per grid row (260 used)
#define PWORDS 468
#define PPOS   (PWORDS*32)         // 14976 padded positions
#define IOU_T  0.4f
#define STK    64
#define BATCH  6

// Per-position predecessor masks (padded layout): x=dy-1, y=dy0, z=dy+1,
// 15 bits each (bit (dx+1)*5+bb). Padding positions never written/read.
__device__ ushort4 g_pm[PPOS];
// Memo: 0=unknown, 1=kept, 2=suppressed. Re-zeroed by decode every launch.
__device__ uint8_t g_st[PPOS];

// ---------------------------------------------------------------------------
// Kernel 1: decode + predecessor masks (proven-exact) + memo reset.
// One thread per (box, dyRow).
// ---------------------------------------------------------------------------
__global__ void decode_kernel(const float* __restrict__ x, float* __restrict__ out)
{
    int id = blockIdx.x * blockDim.x + threadIdx.x;
    if (id >= 3 * NBOX) return;
    int dyI = id / NBOX;            // 0,1,2 -> dy = dyI-1
    int j   = id - dyI * NBOX;

    int cell = j / NB;
    int b    = j - cell * NB;
    int gy   = cell / GW;
    int gx   = cell - gy * GW;

    const float sx = 416.0f / GW;   // 8
    const float sy = 416.0f / GH;   // 8

    const float* p = x + j * 5;
    float c0 = p[0], c1 = p[1], c2 = p[2], c3 = p[3], sj = p[4];

    float cx = (c0 + (float)gx) * sx;
    float w  = c2 * sx;
    float cy = (c1 + (float)gy) * sy;
    float h  = c3 * sy;
    cy = 416.0f - cy;
    float jx1 = cx - w * 0.5f, jy1 = cy - h * 0.5f;
    float jx2 = cx + w * 0.5f, jy2 = cy + h * 0.5f;

    int pos = gy * ROWBITS + gx * 5 + b;

    if (dyI == 1) {
        float* o = out + j * 5;
        o[0] = jx1; o[1] = jy1; o[2] = jx2; o[3] = jy2;
        g_st[pos] = 0;              // memo reset (graph-replay safe)
        // o[4] written by resolve_kernel.
    }

    float aj = fmaxf(jx2 - jx1, 0.0f) * fmaxf(jy2 - jy1, 0.0f);

    unsigned mask = 0;
    int ny = gy + dyI - 1;
    if ((unsigned)ny < GH) {
        #pragma unroll
        for (int dxi = 0; dxi < 3; dxi++) {
            int nx = gx + dxi - 1;
            if ((unsigned)nx >= GW) continue;
            int ncell = ny * GW + nx;
            const float* cp = x + ncell * 25;
            float q[25];
            #pragma unroll
            for (int k = 0; k < 25; k++) q[k] = cp[k];

            #pragma unroll
            for (int bb = 0; bb < NB; bb++) {
                int i = ncell * NB + bb;
                float si = q[bb * 5 + 4];
                bool higher = (si > sj) || (si == sj && i < j);
                float d0 = q[bb * 5 + 0], d1 = q[bb * 5 + 1];
                float d2 = q[bb * 5 + 2], d3 = q[bb * 5 + 3];
                float icx = (d0 + (float)nx) * sx;
                float iw_ = d2 * sx;
                float icy = (d1 + (float)ny) * sy;
                float ih_ = d3 * sy;
                icy = 416.0f - icy;
                float ix1 = icx - iw_ * 0.5f, iy1 = icy - ih_ * 0.5f;
                float ix2 = icx + iw_ * 0.5f, iy2 = icy + ih_ * 0.5f;

                float iw = fmaxf(fminf(ix2, jx2) - fmaxf(ix1, jx1), 0.0f);
                float ih = fmaxf(fminf(iy2, jy2) - fmaxf(iy1, jy1), 0.0f);
                float inter = iw * ih;
                float ai  = fmaxf(ix2 - ix1, 0.0f) * fmaxf(iy2 - iy1, 0.0f);
                float uni = ai + aj - inter;
                float iou = (uni > 0.0f) ? inter / fmaxf(uni, 1e-12f) : 0.0f;
                bool on = (iou > IOU_T) && higher && (i != j);
                mask |= (on ? 1u : 0u) << (dxi * 5 + bb);
            }
        }
    }
    ((unsigned short*)&g_pm[pos])[dyI] = (unsigned short)mask;
}

// ---------------------------------------------------------------------------
// Kernel 2: per-box memoized DFS with batched frontier loads.
// One thread per box, no barriers. Per frame: extract up to BATCH preds,
// issue all memo+mask loads together (MLP), then decide/descend.
// kept[p] = no pred (higher priority, IoU>0.4) that is kept. Well-founded =>
// terminates; unique fixpoint == exact greedy NMS. Memo writes are
// idempotent deterministic values; stale reads only cause recomputation.
// ---------------------------------------------------------------------------
__global__ void __launch_bounds__(256)
resolve_kernel(const float* __restrict__ x, float* __restrict__ out)
{
    int j = blockIdx.x * blockDim.x + threadIdx.x;
    if (j >= NBOX) return;
    int row = j / 260;
    int rem = j - row * 260;
    int pos = row * ROWBITS + rem;

    volatile uint8_t* st = g_st;

    ushort4 pm = __ldg(&g_pm[pos]);
    uint64_t m0 = (uint64_t)pm.x | ((uint64_t)pm.y << 16) | ((uint64_t)pm.z << 32);

    int res;
    if (m0 == 0ull) {
        res = 1;
        st[pos] = 1;
    } else {
        int pre = st[pos];
        if (pre) {
            res = pre;
        } else {
            int      fpos[STK], fpb[STK];
            uint64_t frem[STK];
            fpos[0] = pos;
            fpb[0]  = pos - (rem % 5) - ROWBITS - 5;
            frem[0] = m0;
            int sp = 1;
            res = 0;
            while (sp > 0) {
                uint64_t m = frem[sp - 1];
                int fin = 0;
                if (m == 0ull) {
                    fin = 1;                       // no kept pred -> kept
                } else {
                    // --- batch-extract up to BATCH preds ---
                    int      pl[BATCH];
                    uint64_t bit[BATCH];
                    int np = 0;
                    uint64_t mm = m;
                    while (mm && np < BATCH) {
                        int k = __ffsll((long long)mm) - 1;
                        bit[np] = mm & (~mm + 1ull);
                        mm &= mm - 1;
                        int q = k & 15;
                        pl[np] = fpb[sp - 1] + (k >> 4) * ROWBITS + q;
                        np++;
                    }
                    // --- issue all loads together (independent -> MLP) ---
                    uint8_t sv[BATCH];
                    #pragma unroll
                    for (int i = 0; i < BATCH; i++)
                        sv[i] = (i < np) ? st[pl[i]] : (uint8_t)2;
                    ushort4 pp[BATCH];
                    #pragma unroll
                    for (int i = 0; i < BATCH; i++)
                        pp[i] = (i < np) ? __ldg(&g_pm[pl[i]])
                                         : make_ushort4(0, 0, 0, 0);

                    // --- evaluate batch ---
                    uint64_t rem2 = mm;            // leftover beyond batch
                    int push = -1;
                    uint64_t childm = 0;
                    #pragma unroll
                    for (int i = 0; i < BATCH; i++) {
                        if (i >= np || fin) continue;
                        if (sv[i] == 1) { fin = 2; continue; }   // kept pred
                        if (sv[i] == 2) continue;                // suppressed
                        uint64_t m2 = (uint64_t)pp[i].x
                                    | ((uint64_t)pp[i].y << 16)
                                    | ((uint64_t)pp[i].z << 32);
                        if (m2 == 0ull) {           // pred has no preds -> kept
                            st[pl[i]] = 1;
                            fin = 2;
                            continue;
                        }
                        if (push < 0) { push = i; childm = m2; }
                        else rem2 |= bit[i];        // recheck after child
                    }
                    if (!fin) {
                        if (push < 0) {
                            fin = 1;                // all preds suppressed
                        } else if (sp < STK) {
                            frem[sp - 1] = rem2;
                            int pred = pl[push];
                            int rp   = pred % ROWBITS;
                            int bb   = rp % 5;
                            fpos[sp] = pred;
                            fpb[sp]  = pred - bb - ROWBITS - 5;
                            frem[sp] = childm;
                            sp++;
                            continue;               // descend
                        } else {
                            // Overflow fallback: pred's own thread decides it
                            // (terminates by induction on priority rank).
                            int v;
                            do { v = st[pl[push]]; } while (v == 0);
                            if (v == 1) fin = 2;
                            else { frem[sp - 1] = rem2; continue; }
                        }
                    }
                }
                // --- pop / propagate ---
                st[fpos[sp - 1]] = (uint8_t)fin;
                sp--;
                if (sp == 0) {
                    res = fin;
                } else if (fin == 1) {              // kept child -> parent supp
                    st[fpos[sp - 1]] = 2;
                    sp--;
                    if (sp == 0) res = 2;
                }
                // fin == 2 with sp > 0: parent re-evaluates remaining mask
            }
        }
    }

    out[j * 5 + 4] = (res == 1) ? __ldg(&x[j * 5 + 4]) : 0.0f;
}

// ---------------------------------------------------------------------------
extern "C" void kernel_launch(void* const* d_in, const int* in_sizes, int n_in,
                              void* d_out, int out_size)
{
    const float* x   = (const float*)d_in[0];
    float*       out = (float*)d_out;

    decode_kernel<<<(3 * NBOX + 255) / 256, 256>>>(x, out);
    resolve_kernel<<<(NBOX + 255) / 256, 256>>>(x, out);
}